// round 15
// baseline (speedup 1.0000x reference)
#include <cuda_runtime.h>
#include <math.h>

#define NN 50000
#define EE 800000
#define INDIM 128
#define EDDIM 32
#define NH 4
#define HCDIM 64
#define NG 64
#define SCAN_B 256
#define NBLK ((NN + SCAN_B - 1) / SCAN_B)   // 196
#define GR 256                               // gemm rows per block

// ------------------------- scratch (device globals) -------------------------
static __device__ __align__(16) float    g_xw[NN * HCDIM];
static __device__ __align__(16) float    g_h1[NN * HCDIM];
static __device__ __align__(16) float    g_alsrc[NN * NH];
static __device__ __align__(16) float    g_aldst[NN * NH];
static __device__ __align__(16) float    g_ale[2][(size_t)EE * NH];
static __device__ __align__(16) float    g_pool[NG * HCDIM];
static __device__ __align__(16) int      g_src[EE];
static __device__ __align__(16) int      g_dst[EE];
static __device__ __align__(16) int      g_ssrc[EE];   // src sorted by dst (CSR)
static __device__ __align__(16) int      g_epos[EE];   // original edge -> CSR slot
static __device__ __align__(16) int      g_row[NN + 1];
static __device__ __align__(16) int      g_woff[NN];
static __device__ __align__(16) int      g_cntI[NN];
static __device__ __align__(16) int      g_batch[NN];
static __device__ __align__(16) int      g_bsum[256];
static __device__ __align__(16) int      g_bpre[256];
static __device__           int          g_is32;

// ------------------------- helpers -------------------------
__device__ __forceinline__ float lrelu(float a) { return a > 0.f ? a : 0.2f * a; }

__device__ __forceinline__ unsigned long long bcast2(float v) {
    unsigned long long r;
    asm("mov.b64 %0, {%1, %1};" : "=l"(r) : "f"(v));
    return r;
}
__device__ __forceinline__ void ffma2(unsigned long long& d, unsigned long long a, unsigned long long b) {
    asm("fma.rn.f32x2 %0, %1, %2, %0;" : "+l"(d) : "l"(a), "l"(b));
}
__device__ __forceinline__ float2 unpack2(unsigned long long p) {
    float lo, hi;
    asm("mov.b64 {%0, %1}, %2;" : "=f"(lo), "=f"(hi) : "l"(p));
    return make_float2(lo, hi);
}

// ------------------------- setup kernels -------------------------
// zero counters/pool; block 0 additionally detects the index dtype.
// int64 little-endian layout: every odd 32-bit word is 0 (indices < 50000).
__global__ void k_init(const unsigned* __restrict__ ei_raw) {
    int i = blockIdx.x * blockDim.x + threadIdx.x;
    if (i < NN) g_cntI[i] = 0;
    if (i < NG * HCDIM) g_pool[i] = 0.f;
    if (blockIdx.x == 0) {
        __shared__ int nz;
        if (threadIdx.x == 0) nz = 0;
        __syncthreads();
        int loc = 0;
        for (int k = threadIdx.x; k < 4096; k += 256)
            if (ei_raw[2 * k + 1] != 0u) loc = 1;
        if (loc) nz = 1;
        __syncthreads();
        if (threadIdx.x == 0) g_is32 = nz;
    }
}

__global__ void k_cvt(const void* __restrict__ ei_raw, const void* __restrict__ batch_raw) {
    int i = blockIdx.x * blockDim.x + threadIdx.x;
    int f = g_is32;
    if (i < EE) {
        int s, d;
        if (f) {
            s = ((const int*)ei_raw)[i];
            d = ((const int*)ei_raw)[EE + i];
        } else {
            s = (int)((const long long*)ei_raw)[i];
            d = (int)((const long long*)ei_raw)[EE + i];
        }
        g_src[i] = s;
        g_dst[i] = d;
        atomicAdd(&g_cntI[d], 1);
    }
    if (i < NN) {
        g_batch[i] = f ? ((const int*)batch_raw)[i]
                       : (int)((const long long*)batch_raw)[i];
    }
}

// ---- 3-phase parallel exclusive scan of g_cntI -> g_row / g_woff ----
__global__ void k_scan1() {
    __shared__ int sh[SCAN_B];
    int b = blockIdx.x, t = threadIdx.x;
    int i = b * SCAN_B + t;
    sh[t] = (i < NN) ? g_cntI[i] : 0;
    __syncthreads();
#pragma unroll
    for (int off = SCAN_B / 2; off; off >>= 1) {
        if (t < off) sh[t] += sh[t + off];
        __syncthreads();
    }
    if (t == 0) g_bsum[b] = sh[0];
}

__global__ void k_scan2() {   // 1 block, 256 threads; NBLK <= 256
    __shared__ int sh[256];
    int t = threadIdx.x;
    int v = (t < NBLK) ? g_bsum[t] : 0;
    sh[t] = v;
    __syncthreads();
#pragma unroll
    for (int off = 1; off < 256; off <<= 1) {
        int u = (t >= off) ? sh[t - off] : 0;
        __syncthreads();
        sh[t] += u;
        __syncthreads();
    }
    g_bpre[t] = sh[t] - v;           // exclusive
    if (t == 255) g_row[NN] = sh[255];
}

__global__ void k_scan3() {
    __shared__ int sh[SCAN_B];
    int b = blockIdx.x, t = threadIdx.x;
    int i = b * SCAN_B + t;
    int v = (i < NN) ? g_cntI[i] : 0;
    sh[t] = v;
    __syncthreads();
#pragma unroll
    for (int off = 1; off < SCAN_B; off <<= 1) {
        int u = (t >= off) ? sh[t - off] : 0;
        __syncthreads();
        sh[t] += u;
        __syncthreads();
    }
    if (i < NN) {
        int ex = g_bpre[b] + sh[t] - v;
        g_row[i] = ex;
        g_woff[i] = ex;
    }
}

__global__ void k_scatter() {
    int e = blockIdx.x * blockDim.x + threadIdx.x;
    if (e >= EE) return;
    int d = g_dst[e];
    int pos = atomicAdd(&g_woff[d], 1);
    g_epos[e] = pos;
    g_ssrc[pos] = g_src[e];
}

// al_e for both layers, written in CSR order. The 256-entry ve table
// (ve[l][d*4+h] = sum_c We_l[d, h*16+c] * ae_l[h, c]) is recomputed in the
// smem prologue of every block (16 FMA/thread, L2-cached inputs).
__global__ void k_ale(const float* __restrict__ ea,
                      const float* __restrict__ We1, const float* __restrict__ ae1,
                      const float* __restrict__ We2, const float* __restrict__ ae2) {
    __shared__ float vs[2 * EDDIM * NH];   // 256 floats
    {
        int t = threadIdx.x;               // 256 threads
        int l = t >> 7, r = t & 127, d = r >> 2, h = r & 3;
        const float* We = l ? We2 : We1;
        const float* ae = l ? ae2 : ae1;
        float s = 0.f;
#pragma unroll
        for (int c = 0; c < 16; c++)
            s += __ldg(&We[d * 64 + h * 16 + c]) * __ldg(&ae[h * 16 + c]);
        vs[t] = s;
    }
    __syncthreads();
    int e = blockIdx.x * blockDim.x + threadIdx.x;
    if (e >= EE) return;
    float ev[32];
    const float4* ep = (const float4*)(ea + (size_t)e * EDDIM);
#pragma unroll
    for (int q = 0; q < 8; q++) {
        float4 v = ep[q];
        ev[4 * q] = v.x; ev[4 * q + 1] = v.y; ev[4 * q + 2] = v.z; ev[4 * q + 3] = v.w;
    }
    float a1x = 0, a1y = 0, a1z = 0, a1w = 0;
    float a2x = 0, a2y = 0, a2z = 0, a2w = 0;
#pragma unroll
    for (int d = 0; d < 32; d++) {
        float x = ev[d];
        float4 w1 = *(const float4*)&vs[d * 4];
        float4 w2 = *(const float4*)&vs[128 + d * 4];
        a1x += x * w1.x; a1y += x * w1.y; a1z += x * w1.z; a1w += x * w1.w;
        a2x += x * w2.x; a2y += x * w2.y; a2z += x * w2.z; a2w += x * w2.w;
    }
    int pos = g_epos[e];
    *(float4*)&g_ale[0][(size_t)pos * 4] = make_float4(a1x, a1y, a1z, a1w);
    *(float4*)&g_ale[1][(size_t)pos * 4] = make_float4(a2x, a2y, a2z, a2w);
}

// ---- barrier-free GEMM: W resident in smem, X streamed via LDG broadcast ----
// (unchanged from round 14 — profiled control)
template <int KIN>
__global__ void __launch_bounds__(256, 2)
k_gemm(const float* __restrict__ Xext, const float* __restrict__ W,
       const float* __restrict__ as_, const float* __restrict__ ad_,
       int use_h1) {
    __shared__ float Ws[KIN * HCDIM];    // 32KB (KIN=128) / 16KB (KIN=64)
    const float* X = use_h1 ? g_h1 : Xext;
    int t = threadIdx.x;
    for (int i = t; i < KIN * 16; i += 256)
        ((float4*)Ws)[i] = ((const float4*)W)[i];
    __syncthreads();

    int rg = t >> 3;          // 0..31
    int cg = t & 7;           // 0..7
    int row0 = blockIdx.x * GR;
    int rbase = row0 + rg * 8;
    unsigned long long acc2[8][4];
#pragma unroll
    for (int i = 0; i < 8; i++)
#pragma unroll
        for (int p = 0; p < 4; p++) acc2[i][p] = 0ull;

#pragma unroll 2
    for (int q = 0; q < KIN / 4; q++) {
        float4 xq[8];
#pragma unroll
        for (int i = 0; i < 8; i++) {
            int grow = rbase + i;
            xq[i] = (grow < NN) ? __ldg((const float4*)&X[(size_t)grow * KIN + q * 4])
                                : make_float4(0.f, 0.f, 0.f, 0.f);
        }
#pragma unroll
        for (int v = 0; v < 4; v++) {
            int k = q * 4 + v;
            ulonglong2 w01 = *(const ulonglong2*)&Ws[k * HCDIM + cg * 8];
            ulonglong2 w23 = *(const ulonglong2*)&Ws[k * HCDIM + cg * 8 + 4];
#pragma unroll
            for (int i = 0; i < 8; i++) {
                float xv = (v == 0) ? xq[i].x : (v == 1) ? xq[i].y : (v == 2) ? xq[i].z : xq[i].w;
                unsigned long long xb = bcast2(xv);
                ffma2(acc2[i][0], xb, w01.x);
                ffma2(acc2[i][1], xb, w01.y);
                ffma2(acc2[i][2], xb, w23.x);
                ffma2(acc2[i][3], xb, w23.y);
            }
        }
    }

    float av[8], dv[8];
#pragma unroll
    for (int j = 0; j < 8; j++) {
        av[j] = __ldg(&as_[cg * 8 + j]);
        dv[j] = __ldg(&ad_[cg * 8 + j]);
    }
    int head = cg >> 1;
#pragma unroll
    for (int i = 0; i < 8; i++) {
        float2 c01 = unpack2(acc2[i][0]);
        float2 c23 = unpack2(acc2[i][1]);
        float2 c45 = unpack2(acc2[i][2]);
        float2 c67 = unpack2(acc2[i][3]);
        float a[8] = {c01.x, c01.y, c23.x, c23.y, c45.x, c45.y, c67.x, c67.y};
        float sp = 0.f, dp = 0.f;
#pragma unroll
        for (int j = 0; j < 8; j++) { sp += a[j] * av[j]; dp += a[j] * dv[j]; }
        sp += __shfl_xor_sync(0xffffffffu, sp, 1);
        dp += __shfl_xor_sync(0xffffffffu, dp, 1);
        int grow = rbase + i;
        if (grow < NN) {
            float* o = &g_xw[(size_t)grow * HCDIM + cg * 8];
            *(float4*)o       = make_float4(a[0], a[1], a[2], a[3]);
            *(float4*)(o + 4) = make_float4(a[4], a[5], a[6], a[7]);
            if ((t & 1) == 0) {
                g_alsrc[(size_t)grow * 4 + head] = sp;
                g_aldst[(size_t)grow * 4 + head] = dp;
            }
        }
    }
}

// ------------------------- fused GAT aggregation: one warp per dst node -----
// (exact round-8 version — frozen)
template <int LAYER>
__global__ void k_main(const float* __restrict__ bias,
                       const float* __restrict__ gam, const float* __restrict__ bet) {
    __shared__ float4 s_alpha[8][32];
    int gw = (blockIdx.x * blockDim.x + threadIdx.x) >> 5;
    int lane = threadIdx.x & 31;
    int wl = (threadIdx.x >> 5);
    if (gw >= NN) return;
    int n = gw;
    int r0 = g_row[n], r1 = g_row[n + 1];
    int deg = r1 - r0;
    float4 adst = *(const float4*)&g_aldst[(size_t)n * 4];
    float4 asn  = *(const float4*)&g_alsrc[(size_t)n * 4];

    // ---- phase 1: sum(ale), max(alpha) over incoming edges ----
    float sx = 0.f, sy = 0.f, sz = 0.f, sw = 0.f;
    float mx = -1e30f, my = -1e30f, mz = -1e30f, mw = -1e30f;
    for (int k = r0 + lane; k < r1; k += 32) {
        int s = g_ssrc[k];
        float4 ae = *(const float4*)&g_ale[LAYER][(size_t)k * 4];
        float4 as = *(const float4*)&g_alsrc[(size_t)s * 4];
        sx += ae.x; sy += ae.y; sz += ae.z; sw += ae.w;
        float a0 = lrelu(as.x + adst.x + ae.x);
        float a1 = lrelu(as.y + adst.y + ae.y);
        float a2 = lrelu(as.z + adst.z + ae.z);
        float a3 = lrelu(as.w + adst.w + ae.w);
        if (k < r0 + 32) s_alpha[wl][lane] = make_float4(a0, a1, a2, a3);
        mx = fmaxf(mx, a0); my = fmaxf(my, a1); mz = fmaxf(mz, a2); mw = fmaxf(mw, a3);
    }
#pragma unroll
    for (int o = 16; o; o >>= 1) {
        sx += __shfl_xor_sync(0xffffffffu, sx, o);
        sy += __shfl_xor_sync(0xffffffffu, sy, o);
        sz += __shfl_xor_sync(0xffffffffu, sz, o);
        sw += __shfl_xor_sync(0xffffffffu, sw, o);
        mx = fmaxf(mx, __shfl_xor_sync(0xffffffffu, mx, o));
        my = fmaxf(my, __shfl_xor_sync(0xffffffffu, my, o));
        mz = fmaxf(mz, __shfl_xor_sync(0xffffffffu, mz, o));
        mw = fmaxf(mw, __shfl_xor_sync(0xffffffffu, mw, o));
    }
    float inv = 1.f / (float)(deg > 0 ? deg : 1);
    float ax0 = lrelu(asn.x + adst.x + sx * inv);
    float ax1 = lrelu(asn.y + adst.y + sy * inv);
    float ax2 = lrelu(asn.z + adst.z + sz * inv);
    float ax3 = lrelu(asn.w + adst.w + sw * inv);
    float AX = fmaxf(mx, ax0), AY = fmaxf(my, ax1), AZ = fmaxf(mz, ax2), AW = fmaxf(mw, ax3);
    float e0 = __expf(ax0 - AX), e1 = __expf(ax1 - AY), e2 = __expf(ax2 - AZ), e3 = __expf(ax3 - AW);

    // accumulators: channels c0=lane, c1=lane+32
    bool lo = lane < 16;
    float acc0 = g_xw[(size_t)n * 64 + lane]        * (lo ? e0 : e1);
    float acc1 = g_xw[(size_t)n * 64 + 32 + lane]   * (lo ? e2 : e3);
    float dnx = (lane == 0) ? e0 : 0.f, dny = (lane == 0) ? e1 : 0.f;
    float dnz = (lane == 0) ? e2 : 0.f, dnw = (lane == 0) ? e3 : 0.f;

    // ---- phase 2: exp + weighted gather-accumulate ----
    for (int base = r0; base < r1; base += 32) {
        int k = base + lane;
        int s = 0;
        float w0 = 0.f, w1 = 0.f, w2 = 0.f, w3 = 0.f;
        if (k < r1) {
            s = g_ssrc[k];
            float a0, a1, a2, a3;
            if (base == r0) {
                float4 al = s_alpha[wl][lane];
                a0 = al.x; a1 = al.y; a2 = al.z; a3 = al.w;
            } else {
                float4 ae = *(const float4*)&g_ale[LAYER][(size_t)k * 4];
                float4 as = *(const float4*)&g_alsrc[(size_t)s * 4];
                a0 = lrelu(as.x + adst.x + ae.x);
                a1 = lrelu(as.y + adst.y + ae.y);
                a2 = lrelu(as.z + adst.z + ae.z);
                a3 = lrelu(as.w + adst.w + ae.w);
            }
            w0 = __expf(a0 - AX); w1 = __expf(a1 - AY);
            w2 = __expf(a2 - AZ); w3 = __expf(a3 - AW);
            dnx += w0; dny += w1; dnz += w2; dnw += w3;
        }
        int m = r1 - base; if (m > 32) m = 32;
        for (int j = 0; j < m; j++) {
            int   sj = __shfl_sync(0xffffffffu, s, j);
            float qx = __shfl_sync(0xffffffffu, w0, j);
            float qy = __shfl_sync(0xffffffffu, w1, j);
            float qz = __shfl_sync(0xffffffffu, w2, j);
            float qw = __shfl_sync(0xffffffffu, w3, j);
            float wa = lo ? qx : qy;
            float wb = lo ? qz : qw;
            acc0 += wa * __ldg(&g_xw[(size_t)sj * 64 + lane]);
            acc1 += wb * __ldg(&g_xw[(size_t)sj * 64 + 32 + lane]);
        }
    }
#pragma unroll
    for (int o = 16; o; o >>= 1) {
        dnx += __shfl_xor_sync(0xffffffffu, dnx, o);
        dny += __shfl_xor_sync(0xffffffffu, dny, o);
        dnz += __shfl_xor_sync(0xffffffffu, dnz, o);
        dnw += __shfl_xor_sync(0xffffffffu, dnw, o);
    }
    float d0 = (lo ? dnx : dny) + 1e-16f;
    float d1 = (lo ? dnz : dnw) + 1e-16f;
    float v0 = fmaxf(acc0 / d0 + __ldg(&bias[lane]), 0.f);
    float v1 = fmaxf(acc1 / d1 + __ldg(&bias[lane + 32]), 0.f);

    if (LAYER == 0) {
        float su = v0 + v1, qu = v0 * v0 + v1 * v1;
#pragma unroll
        for (int o = 16; o; o >>= 1) {
            su += __shfl_xor_sync(0xffffffffu, su, o);
            qu += __shfl_xor_sync(0xffffffffu, qu, o);
        }
        float mean = su * (1.f / 64.f);
        float var = qu * (1.f / 64.f) - mean * mean;
        float rs = rsqrtf(var + 1e-5f);
        g_h1[(size_t)n * 64 + lane]      = (v0 - mean) * rs * __ldg(&gam[lane])      + __ldg(&bet[lane]);
        g_h1[(size_t)n * 64 + 32 + lane] = (v1 - mean) * rs * __ldg(&gam[lane + 32]) + __ldg(&bet[lane + 32]);
    } else {
        int g = g_batch[n];
        atomicMax((int*)&g_pool[g * 64 + lane],      __float_as_int(v0));
        atomicMax((int*)&g_pool[g * 64 + 32 + lane], __float_as_int(v1));
    }
}

// MLP head
__global__ void k_final(const float* __restrict__ fw1, const float* __restrict__ fb1,
                        const float* __restrict__ g2, const float* __restrict__ be2,
                        const float* __restrict__ fw2, const float* __restrict__ fb2,
                        float* __restrict__ out) {
    int g = blockIdx.x, j = threadIdx.x;   // 32 threads
    float z = fb1[j];
#pragma unroll 8
    for (int k = 0; k < 64; k++) z += g_pool[g * 64 + k] * fw1[k * 32 + j];
    float s = z;
#pragma unroll
    for (int o = 16; o; o >>= 1) s += __shfl_xor_sync(0xffffffffu, s, o);
    float mean = s * (1.f / 32.f);
    float dd = z - mean;
    float q = dd * dd;
#pragma unroll
    for (int o = 16; o; o >>= 1) q += __shfl_xor_sync(0xffffffffu, q, o);
    float var = q * (1.f / 32.f);
    float y = fmaxf(dd * rsqrtf(var + 1e-5f) * g2[j] + be2[j], 0.f);
    float p0 = y * fw2[j * 2 + 0];
    float p1 = y * fw2[j * 2 + 1];
#pragma unroll
    for (int o = 16; o; o >>= 1) {
        p0 += __shfl_xor_sync(0xffffffffu, p0, o);
        p1 += __shfl_xor_sync(0xffffffffu, p1, o);
    }
    if (j == 0) {
        float z0 = p0 + fb2[0], z1 = p1 + fb2[1];
        float m = fmaxf(z0, z1);
        float lse = m + __logf(__expf(z0 - m) + __expf(z1 - m));
        out[g * 2 + 0] = z0 - lse;
        out[g * 2 + 1] = z1 - lse;
    }
}

// ------------------------- launch -------------------------
extern "C" void kernel_launch(void* const* d_in, const int* in_sizes, int n_in,
                              void* d_out, int out_size) {
    (void)in_sizes; (void)n_in; (void)out_size;
    const float* x   = (const float*)d_in[0];
    const float* ea  = (const float*)d_in[1];
    const float* W1  = (const float*)d_in[2];
    const float* as1 = (const float*)d_in[3];
    const float* ad1 = (const float*)d_in[4];
    const float* We1 = (const float*)d_in[5];
    const float* ae1 = (const float*)d_in[6];
    const float* b1  = (const float*)d_in[7];
    const float* W2  = (const float*)d_in[8];
    const float* as2 = (const float*)d_in[9];
    const float* ad2 = (const float*)d_in[10];
    const float* We2 = (const float*)d_in[11];
    const float* ae2 = (const float*)d_in[12];
    const float* b2  = (const float*)d_in[13];
    const float* g1  = (const float*)d_in[14];
    const float* be1 = (const float*)d_in[15];
    const float* fw1 = (const float*)d_in[16];
    const float* fb1 = (const float*)d_in[17];
    const float* g2  = (const float*)d_in[18];
    const float* be2 = (const float*)d_in[19];
    const float* fw2 = (const float*)d_in[20];
    const float* fb2 = (const float*)d_in[21];
    const void* ei_raw    = d_in[22];
    const void* batch_raw = d_in[23];
    float* out = (float*)d_out;

    const int TB = 256;
    int nb_nh = (NN * NH + TB - 1) / TB;
    int nb_e  = (EE + TB - 1) / TB;
    int nb_w  = (NN * 32 + TB - 1) / TB;     // warp per node
    int nb_g  = (NN + GR - 1) / GR;          // gemm blocks (196)

    k_init<<<nb_nh, TB>>>((const unsigned*)ei_raw);
    k_cvt<<<nb_e, TB>>>(ei_raw, batch_raw);
    k_scan1<<<NBLK, SCAN_B>>>();
    // 4th launch stays k_gemm<128> (profiled control; independent of scan chain)
    k_gemm<INDIM><<<nb_g, TB>>>(x, W1, as1, ad1, 0);
    k_scan2<<<1, 256>>>();
    k_scan3<<<NBLK, SCAN_B>>>();
    k_scatter<<<nb_e, TB>>>();
    k_ale<<<nb_e, TB>>>(ea, We1, ae1, We2, ae2);

    // ---- layer 1 aggregation ----
    k_main<0><<<nb_w, TB>>>(b1, g1, be1);

    // ---- layer 2 ----
    k_gemm<HCDIM><<<nb_g, TB>>>(nullptr, W2, as2, ad2, 1);
    k_main<1><<<nb_w, TB>>>(b2, nullptr, nullptr);

    // ---- head ----
    k_final<<<NG, 32>>>(fw1, fb1, g2, be2, fw2, fb2, out);
}

// round 16
// speedup vs baseline: 1.0810x; 1.0810x over previous
#include <cuda_runtime.h>
#include <math.h>

#define NN 50000
#define EE 800000
#define INDIM 128
#define EDDIM 32
#define NH 4
#define HCDIM 64
#define NG 64
#define SCAN_B 256
#define NBLK ((NN + SCAN_B - 1) / SCAN_B)   // 196
#define GR 256                               // gemm rows per block

// ------------------------- scratch (device globals) -------------------------
static __device__ __align__(16) float    g_xw[NN * HCDIM];
static __device__ __align__(16) float    g_h1[NN * HCDIM];
static __device__ __align__(16) float    g_alsrc[NN * NH];
static __device__ __align__(16) float    g_aldst[NN * NH];
static __device__ __align__(16) float    g_ale[2][(size_t)EE * NH];
static __device__ __align__(16) float    g_ve[2][EDDIM * NH];
static __device__ __align__(16) float    g_pool[NG * HCDIM];
static __device__ __align__(16) int      g_src[EE];
static __device__ __align__(16) int      g_dst[EE];
static __device__ __align__(16) int      g_ssrc[EE];   // src sorted by dst (CSR)
static __device__ __align__(16) int      g_epos[EE];   // original edge -> CSR slot
static __device__ __align__(16) int      g_row[NN + 1];
static __device__ __align__(16) int      g_woff[NN];
static __device__ __align__(16) int      g_cntI[NN];
static __device__ __align__(16) int      g_batch[NN];
static __device__ __align__(16) int      g_bsum[256];
static __device__ __align__(16) int      g_bpre[256];
static __device__           int          g_is32;

// ------------------------- helpers -------------------------
__device__ __forceinline__ float lrelu(float a) { return a > 0.f ? a : 0.2f * a; }

__device__ __forceinline__ unsigned long long bcast2(float v) {
    unsigned long long r;
    asm("mov.b64 %0, {%1, %1};" : "=l"(r) : "f"(v));
    return r;
}
__device__ __forceinline__ void ffma2(unsigned long long& d, unsigned long long a, unsigned long long b) {
    asm("fma.rn.f32x2 %0, %1, %2, %0;" : "+l"(d) : "l"(a), "l"(b));
}
__device__ __forceinline__ float2 unpack2(unsigned long long p) {
    float lo, hi;
    asm("mov.b64 {%0, %1}, %2;" : "=f"(lo), "=f"(hi) : "l"(p));
    return make_float2(lo, hi);
}

// ------------------------- setup kernels -------------------------
__global__ void k_zero() {
    int i = blockIdx.x * blockDim.x + threadIdx.x;
    if (i < NN) g_cntI[i] = 0;
    if (i < NG * HCDIM) g_pool[i] = 0.f;
}

// int64 little-endian layout: every odd 32-bit word is 0 (indices < 50000).
__global__ void k_detect(const unsigned* __restrict__ ei_raw) {
    __shared__ int nz;
    if (threadIdx.x == 0) nz = 0;
    __syncthreads();
    for (int k = threadIdx.x; k < 4096; k += 256)
        if (ei_raw[2 * k + 1] != 0u) nz = 1;
    __syncthreads();
    if (threadIdx.x == 0) g_is32 = nz;
}

__global__ void k_cvt(const void* __restrict__ ei_raw, const void* __restrict__ batch_raw) {
    int i = blockIdx.x * blockDim.x + threadIdx.x;
    int f = g_is32;
    if (i < EE) {
        int s, d;
        if (f) {
            s = ((const int*)ei_raw)[i];
            d = ((const int*)ei_raw)[EE + i];
        } else {
            s = (int)((const long long*)ei_raw)[i];
            d = (int)((const long long*)ei_raw)[EE + i];
        }
        g_src[i] = s;
        g_dst[i] = d;
        atomicAdd(&g_cntI[d], 1);
    }
    if (i < NN) {
        g_batch[i] = f ? ((const int*)batch_raw)[i]
                       : (int)((const long long*)batch_raw)[i];
    }
}

// ---- 3-phase parallel exclusive scan of g_cntI -> g_row / g_woff ----
__global__ void k_scan1() {
    __shared__ int sh[SCAN_B];
    int b = blockIdx.x, t = threadIdx.x;
    int i = b * SCAN_B + t;
    sh[t] = (i < NN) ? g_cntI[i] : 0;
    __syncthreads();
#pragma unroll
    for (int off = SCAN_B / 2; off; off >>= 1) {
        if (t < off) sh[t] += sh[t + off];
        __syncthreads();
    }
    if (t == 0) g_bsum[b] = sh[0];
}

__global__ void k_scan2() {   // 1 block, 256 threads; NBLK <= 256
    __shared__ int sh[256];
    int t = threadIdx.x;
    int v = (t < NBLK) ? g_bsum[t] : 0;
    sh[t] = v;
    __syncthreads();
#pragma unroll
    for (int off = 1; off < 256; off <<= 1) {
        int u = (t >= off) ? sh[t - off] : 0;
        __syncthreads();
        sh[t] += u;
        __syncthreads();
    }
    g_bpre[t] = sh[t] - v;           // exclusive
    if (t == 255) g_row[NN] = sh[255];
}

__global__ void k_scan3() {
    __shared__ int sh[SCAN_B];
    int b = blockIdx.x, t = threadIdx.x;
    int i = b * SCAN_B + t;
    int v = (i < NN) ? g_cntI[i] : 0;
    sh[t] = v;
    __syncthreads();
#pragma unroll
    for (int off = 1; off < SCAN_B; off <<= 1) {
        int u = (t >= off) ? sh[t - off] : 0;
        __syncthreads();
        sh[t] += u;
        __syncthreads();
    }
    if (i < NN) {
        int ex = g_bpre[b] + sh[t] - v;
        g_row[i] = ex;
        g_woff[i] = ex;
    }
}

__global__ void k_scatter() {
    int e = blockIdx.x * blockDim.x + threadIdx.x;
    if (e >= EE) return;
    int d = g_dst[e];
    int pos = atomicAdd(&g_woff[d], 1);
    g_epos[e] = pos;
    g_ssrc[pos] = g_src[e];
}

// ve[l][d*4+h] = sum_c We_l[d, h*16+c] * ae_l[h, c]
__global__ void k_ve(const float* __restrict__ We1, const float* __restrict__ ae1,
                     const float* __restrict__ We2, const float* __restrict__ ae2) {
    int t = threadIdx.x;           // 256 threads
    int l = t >> 7, r = t & 127, d = r >> 2, h = r & 3;
    const float* We = l ? We2 : We1;
    const float* ae = l ? ae2 : ae1;
    float s = 0.f;
#pragma unroll
    for (int c = 0; c < 16; c++) s += We[d * 64 + h * 16 + c] * ae[h * 16 + c];
    g_ve[l][d * 4 + h] = s;
}

// al_e for both layers, written in CSR order
__global__ void k_ale(const float* __restrict__ ea) {
    __shared__ float vs[2 * EDDIM * NH];   // 256 floats
    if (threadIdx.x < 256) vs[threadIdx.x] = ((const float*)g_ve)[threadIdx.x];
    __syncthreads();
    int e = blockIdx.x * blockDim.x + threadIdx.x;
    if (e >= EE) return;
    float ev[32];
    const float4* ep = (const float4*)(ea + (size_t)e * EDDIM);
#pragma unroll
    for (int q = 0; q < 8; q++) {
        float4 v = ep[q];
        ev[4 * q] = v.x; ev[4 * q + 1] = v.y; ev[4 * q + 2] = v.z; ev[4 * q + 3] = v.w;
    }
    float a1x = 0, a1y = 0, a1z = 0, a1w = 0;
    float a2x = 0, a2y = 0, a2z = 0, a2w = 0;
#pragma unroll
    for (int d = 0; d < 32; d++) {
        float x = ev[d];
        float4 w1 = *(const float4*)&vs[d * 4];
        float4 w2 = *(const float4*)&vs[128 + d * 4];
        a1x += x * w1.x; a1y += x * w1.y; a1z += x * w1.z; a1w += x * w1.w;
        a2x += x * w2.x; a2y += x * w2.y; a2z += x * w2.z; a2w += x * w2.w;
    }
    int pos = g_epos[e];
    *(float4*)&g_ale[0][(size_t)pos * 4] = make_float4(a1x, a1y, a1z, a1w);
    *(float4*)&g_ale[1][(size_t)pos * 4] = make_float4(a2x, a2y, a2z, a2w);
}

// ---- barrier-free GEMM, 8 rows x 4 cols per thread, 2 column-halves --------
// blockIdx.x = rowblk*2 + colhalf. Block covers 256 rows x 32 cols.
// W slice (KIN x 32) resident in smem; X streamed via LDG same-address bcast.
// Per k: 1 LDS.128 (ulonglong2 = col pairs) + 8 bcast + 16 FFMA2.
template <int KIN>
__global__ void __launch_bounds__(256, 3)
k_gemm(const float* __restrict__ Xext, const float* __restrict__ W,
       const float* __restrict__ as_, const float* __restrict__ ad_,
       int use_h1) {
    __shared__ float Ws[KIN * 32];       // 16KB (KIN=128) / 8KB (KIN=64)
    const float* X = use_h1 ? g_h1 : Xext;
    int t = threadIdx.x;
    int colhalf = blockIdx.x & 1;
    int rowblk  = blockIdx.x >> 1;
    // load W slice: Ws[k*32 + c] = W[k*64 + colhalf*32 + c]
    for (int i = t; i < KIN * 8; i += 256) {
        int k = i >> 3, q = i & 7;
        ((float4*)&Ws[k * 32])[q] = ((const float4*)&W[(size_t)k * HCDIM + colhalf * 32])[q];
    }
    __syncthreads();

    int rg = t >> 3;          // 0..31
    int cg = t & 7;           // 0..7  -> cols colhalf*32 + cg*4 .. +3
    int rbase = rowblk * GR + rg * 8;
    unsigned long long acc2[8][2];
#pragma unroll
    for (int i = 0; i < 8; i++) { acc2[i][0] = 0ull; acc2[i][1] = 0ull; }

#pragma unroll 2
    for (int q = 0; q < KIN / 4; q++) {
        float4 xq[8];
#pragma unroll
        for (int i = 0; i < 8; i++) {
            int grow = rbase + i;
            xq[i] = (grow < NN) ? __ldg((const float4*)&X[(size_t)grow * KIN + q * 4])
                                : make_float4(0.f, 0.f, 0.f, 0.f);
        }
#pragma unroll
        for (int v = 0; v < 4; v++) {
            int k = q * 4 + v;
            ulonglong2 w01 = *(const ulonglong2*)&Ws[k * 32 + cg * 4];
#pragma unroll
            for (int i = 0; i < 8; i++) {
                float xv = (v == 0) ? xq[i].x : (v == 1) ? xq[i].y : (v == 2) ? xq[i].z : xq[i].w;
                unsigned long long xb = bcast2(xv);
                ffma2(acc2[i][0], xb, w01.x);
                ffma2(acc2[i][1], xb, w01.y);
            }
        }
    }

    // alpha partials: this thread's 4 cols belong to head (colhalf*2 + (cg>>2)).
    int cbase = colhalf * 32 + cg * 4;
    float av[4], dv[4];
#pragma unroll
    for (int j = 0; j < 4; j++) {
        av[j] = __ldg(&as_[cbase + j]);
        dv[j] = __ldg(&ad_[cbase + j]);
    }
    int head = cbase >> 4;
#pragma unroll
    for (int i = 0; i < 8; i++) {
        float2 c01 = unpack2(acc2[i][0]);
        float2 c23 = unpack2(acc2[i][1]);
        float a[4] = {c01.x, c01.y, c23.x, c23.y};
        float sp = 0.f, dp = 0.f;
#pragma unroll
        for (int j = 0; j < 4; j++) { sp += a[j] * av[j]; dp += a[j] * dv[j]; }
        // head's 16 cols span the 4 threads cg&~3 .. cg|3 (same rg group)
        sp += __shfl_xor_sync(0xffffffffu, sp, 1);
        dp += __shfl_xor_sync(0xffffffffu, dp, 1);
        sp += __shfl_xor_sync(0xffffffffu, sp, 2);
        dp += __shfl_xor_sync(0xffffffffu, dp, 2);
        int grow = rbase + i;
        if (grow < NN) {
            *(float4*)&g_xw[(size_t)grow * HCDIM + cbase] = make_float4(a[0], a[1], a[2], a[3]);
            if ((cg & 3) == 0) {
                g_alsrc[(size_t)grow * 4 + head] = sp;
                g_aldst[(size_t)grow * 4 + head] = dp;
            }
        }
    }
}

// ------------------------- fused GAT aggregation: one warp per dst node -----
// (exact round-8 version — frozen)
template <int LAYER>
__global__ void k_main(const float* __restrict__ bias,
                       const float* __restrict__ gam, const float* __restrict__ bet) {
    __shared__ float4 s_alpha[8][32];
    int gw = (blockIdx.x * blockDim.x + threadIdx.x) >> 5;
    int lane = threadIdx.x & 31;
    int wl = (threadIdx.x >> 5);
    if (gw >= NN) return;
    int n = gw;
    int r0 = g_row[n], r1 = g_row[n + 1];
    int deg = r1 - r0;
    float4 adst = *(const float4*)&g_aldst[(size_t)n * 4];
    float4 asn  = *(const float4*)&g_alsrc[(size_t)n * 4];

    // ---- phase 1: sum(ale), max(alpha) over incoming edges ----
    float sx = 0.f, sy = 0.f, sz = 0.f, sw = 0.f;
    float mx = -1e30f, my = -1e30f, mz = -1e30f, mw = -1e30f;
    for (int k = r0 + lane; k < r1; k += 32) {
        int s = g_ssrc[k];
        float4 ae = *(const float4*)&g_ale[LAYER][(size_t)k * 4];
        float4 as = *(const float4*)&g_alsrc[(size_t)s * 4];
        sx += ae.x; sy += ae.y; sz += ae.z; sw += ae.w;
        float a0 = lrelu(as.x + adst.x + ae.x);
        float a1 = lrelu(as.y + adst.y + ae.y);
        float a2 = lrelu(as.z + adst.z + ae.z);
        float a3 = lrelu(as.w + adst.w + ae.w);
        if (k < r0 + 32) s_alpha[wl][lane] = make_float4(a0, a1, a2, a3);
        mx = fmaxf(mx, a0); my = fmaxf(my, a1); mz = fmaxf(mz, a2); mw = fmaxf(mw, a3);
    }
#pragma unroll
    for (int o = 16; o; o >>= 1) {
        sx += __shfl_xor_sync(0xffffffffu, sx, o);
        sy += __shfl_xor_sync(0xffffffffu, sy, o);
        sz += __shfl_xor_sync(0xffffffffu, sz, o);
        sw += __shfl_xor_sync(0xffffffffu, sw, o);
        mx = fmaxf(mx, __shfl_xor_sync(0xffffffffu, mx, o));
        my = fmaxf(my, __shfl_xor_sync(0xffffffffu, my, o));
        mz = fmaxf(mz, __shfl_xor_sync(0xffffffffu, mz, o));
        mw = fmaxf(mw, __shfl_xor_sync(0xffffffffu, mw, o));
    }
    float inv = 1.f / (float)(deg > 0 ? deg : 1);
    float ax0 = lrelu(asn.x + adst.x + sx * inv);
    float ax1 = lrelu(asn.y + adst.y + sy * inv);
    float ax2 = lrelu(asn.z + adst.z + sz * inv);
    float ax3 = lrelu(asn.w + adst.w + sw * inv);
    float AX = fmaxf(mx, ax0), AY = fmaxf(my, ax1), AZ = fmaxf(mz, ax2), AW = fmaxf(mw, ax3);
    float e0 = __expf(ax0 - AX), e1 = __expf(ax1 - AY), e2 = __expf(ax2 - AZ), e3 = __expf(ax3 - AW);

    // accumulators: channels c0=lane, c1=lane+32
    bool lo = lane < 16;
    float acc0 = g_xw[(size_t)n * 64 + lane]        * (lo ? e0 : e1);
    float acc1 = g_xw[(size_t)n * 64 + 32 + lane]   * (lo ? e2 : e3);
    float dnx = (lane == 0) ? e0 : 0.f, dny = (lane == 0) ? e1 : 0.f;
    float dnz = (lane == 0) ? e2 : 0.f, dnw = (lane == 0) ? e3 : 0.f;

    // ---- phase 2: exp + weighted gather-accumulate ----
    for (int base = r0; base < r1; base += 32) {
        int k = base + lane;
        int s = 0;
        float w0 = 0.f, w1 = 0.f, w2 = 0.f, w3 = 0.f;
        if (k < r1) {
            s = g_ssrc[k];
            float a0, a1, a2, a3;
            if (base == r0) {
                float4 al = s_alpha[wl][lane];
                a0 = al.x; a1 = al.y; a2 = al.z; a3 = al.w;
            } else {
                float4 ae = *(const float4*)&g_ale[LAYER][(size_t)k * 4];
                float4 as = *(const float4*)&g_alsrc[(size_t)s * 4];
                a0 = lrelu(as.x + adst.x + ae.x);
                a1 = lrelu(as.y + adst.y + ae.y);
                a2 = lrelu(as.z + adst.z + ae.z);
                a3 = lrelu(as.w + adst.w + ae.w);
            }
            w0 = __expf(a0 - AX); w1 = __expf(a1 - AY);
            w2 = __expf(a2 - AZ); w3 = __expf(a3 - AW);
            dnx += w0; dny += w1; dnz += w2; dnw += w3;
        }
        int m = r1 - base; if (m > 32) m = 32;
        for (int j = 0; j < m; j++) {
            int   sj = __shfl_sync(0xffffffffu, s, j);
            float qx = __shfl_sync(0xffffffffu, w0, j);
            float qy = __shfl_sync(0xffffffffu, w1, j);
            float qz = __shfl_sync(0xffffffffu, w2, j);
            float qw = __shfl_sync(0xffffffffu, w3, j);
            float wa = lo ? qx : qy;
            float wb = lo ? qz : qw;
            acc0 += wa * __ldg(&g_xw[(size_t)sj * 64 + lane]);
            acc1 += wb * __ldg(&g_xw[(size_t)sj * 64 + 32 + lane]);
        }
    }
#pragma unroll
    for (int o = 16; o; o >>= 1) {
        dnx += __shfl_xor_sync(0xffffffffu, dnx, o);
        dny += __shfl_xor_sync(0xffffffffu, dny, o);
        dnz += __shfl_xor_sync(0xffffffffu, dnz, o);
        dnw += __shfl_xor_sync(0xffffffffu, dnw, o);
    }
    float d0 = (lo ? dnx : dny) + 1e-16f;
    float d1 = (lo ? dnz : dnw) + 1e-16f;
    float v0 = fmaxf(acc0 / d0 + __ldg(&bias[lane]), 0.f);
    float v1 = fmaxf(acc1 / d1 + __ldg(&bias[lane + 32]), 0.f);

    if (LAYER == 0) {
        float su = v0 + v1, qu = v0 * v0 + v1 * v1;
#pragma unroll
        for (int o = 16; o; o >>= 1) {
            su += __shfl_xor_sync(0xffffffffu, su, o);
            qu += __shfl_xor_sync(0xffffffffu, qu, o);
        }
        float mean = su * (1.f / 64.f);
        float var = qu * (1.f / 64.f) - mean * mean;
        float rs = rsqrtf(var + 1e-5f);
        g_h1[(size_t)n * 64 + lane]      = (v0 - mean) * rs * __ldg(&gam[lane])      + __ldg(&bet[lane]);
        g_h1[(size_t)n * 64 + 32 + lane] = (v1 - mean) * rs * __ldg(&gam[lane + 32]) + __ldg(&bet[lane + 32]);
    } else {
        int g = g_batch[n];
        atomicMax((int*)&g_pool[g * 64 + lane],      __float_as_int(v0));
        atomicMax((int*)&g_pool[g * 64 + 32 + lane], __float_as_int(v1));
    }
}

// MLP head
__global__ void k_final(const float* __restrict__ fw1, const float* __restrict__ fb1,
                        const float* __restrict__ g2, const float* __restrict__ be2,
                        const float* __restrict__ fw2, const float* __restrict__ fb2,
                        float* __restrict__ out) {
    int g = blockIdx.x, j = threadIdx.x;   // 32 threads
    float z = fb1[j];
#pragma unroll 8
    for (int k = 0; k < 64; k++) z += g_pool[g * 64 + k] * fw1[k * 32 + j];
    float s = z;
#pragma unroll
    for (int o = 16; o; o >>= 1) s += __shfl_xor_sync(0xffffffffu, s, o);
    float mean = s * (1.f / 32.f);
    float dd = z - mean;
    float q = dd * dd;
#pragma unroll
    for (int o = 16; o; o >>= 1) q += __shfl_xor_sync(0xffffffffu, q, o);
    float var = q * (1.f / 32.f);
    float y = fmaxf(dd * rsqrtf(var + 1e-5f) * g2[j] + be2[j], 0.f);
    float p0 = y * fw2[j * 2 + 0];
    float p1 = y * fw2[j * 2 + 1];
#pragma unroll
    for (int o = 16; o; o >>= 1) {
        p0 += __shfl_xor_sync(0xffffffffu, p0, o);
        p1 += __shfl_xor_sync(0xffffffffu, p1, o);
    }
    if (j == 0) {
        float z0 = p0 + fb2[0], z1 = p1 + fb2[1];
        float m = fmaxf(z0, z1);
        float lse = m + __logf(__expf(z0 - m) + __expf(z1 - m));
        out[g * 2 + 0] = z0 - lse;
        out[g * 2 + 1] = z1 - lse;
    }
}

// ------------------------- launch -------------------------
extern "C" void kernel_launch(void* const* d_in, const int* in_sizes, int n_in,
                              void* d_out, int out_size) {
    (void)in_sizes; (void)n_in; (void)out_size;
    const float* x   = (const float*)d_in[0];
    const float* ea  = (const float*)d_in[1];
    const float* W1  = (const float*)d_in[2];
    const float* as1 = (const float*)d_in[3];
    const float* ad1 = (const float*)d_in[4];
    const float* We1 = (const float*)d_in[5];
    const float* ae1 = (const float*)d_in[6];
    const float* b1  = (const float*)d_in[7];
    const float* W2  = (const float*)d_in[8];
    const float* as2 = (const float*)d_in[9];
    const float* ad2 = (const float*)d_in[10];
    const float* We2 = (const float*)d_in[11];
    const float* ae2 = (const float*)d_in[12];
    const float* b2  = (const float*)d_in[13];
    const float* g1  = (const float*)d_in[14];
    const float* be1 = (const float*)d_in[15];
    const float* fw1 = (const float*)d_in[16];
    const float* fb1 = (const float*)d_in[17];
    const float* g2  = (const float*)d_in[18];
    const float* be2 = (const float*)d_in[19];
    const float* fw2 = (const float*)d_in[20];
    const float* fb2 = (const float*)d_in[21];
    const void* ei_raw    = d_in[22];
    const void* batch_raw = d_in[23];
    float* out = (float*)d_out;

    const int TB = 256;
    int nb_nh = (NN * NH + TB - 1) / TB;
    int nb_e  = (EE + TB - 1) / TB;
    int nb_w  = (NN * 32 + TB - 1) / TB;       // warp per node
    int nb_g  = ((NN + GR - 1) / GR) * 2;      // gemm blocks (196 rowblks x 2 colhalves)

    k_zero<<<nb_nh, TB>>>();
    k_detect<<<1, 256>>>((const unsigned*)ei_raw);
    k_cvt<<<nb_e, TB>>>(ei_raw, batch_raw);
    // 4th launch stays k_gemm<128> (profiled control)
    k_gemm<INDIM><<<nb_g, TB>>>(x, W1, as1, ad1, 0);
    k_scan1<<<NBLK, SCAN_B>>>();
    k_scan2<<<1, 256>>>();
    k_scan3<<<NBLK, SCAN_B>>>();
    k_scatter<<<nb_e, TB>>>();
    k_ve<<<1, 256>>>(We1, ae1, We2, ae2);
    k_ale<<<nb_e, TB>>>(ea);

    // ---- layer 1 aggregation ----
    k_main<0><<<nb_w, TB>>>(b1, g1, be1);

    // ---- layer 2 ----
    k_gemm<HCDIM><<<nb_g, TB>>>(nullptr, W2, as2, ad2, 1);
    k_main<1><<<nb_w, TB>>>(b2, nullptr, nullptr);

    // ---- head ----
    k_final<<<NG, 32>>>(fw1, fb1, g2, be2, fw2, fb2, out);
}

// round 17
// speedup vs baseline: 1.0870x; 1.0055x over previous
#include <cuda_runtime.h>
#include <math.h>

#define NN 50000
#define EE 800000
#define INDIM 128
#define EDDIM 32
#define NH 4
#define HCDIM 64
#define NG 64
#define SCAN_B 256
#define NBLK ((NN + SCAN_B - 1) / SCAN_B)   // 196
#define GR 256                               // gemm rows per block

// ------------------------- scratch (device globals) -------------------------
static __device__ __align__(16) float    g_xw[NN * HCDIM];
static __device__ __align__(16) float    g_h1[NN * HCDIM];
static __device__ __align__(16) float    g_alsrc[NN * NH];
static __device__ __align__(16) float    g_aldst[NN * NH];
static __device__ __align__(16) float    g_ale[2][(size_t)EE * NH];
static __device__ __align__(16) float    g_ve[2][EDDIM * NH];
static __device__ __align__(16) float    g_pool[NG * HCDIM];
static __device__ __align__(16) int      g_src[EE];
static __device__ __align__(16) int      g_dst[EE];
static __device__ __align__(16) int      g_ssrc[EE];   // src sorted by dst (CSR)
static __device__ __align__(16) int      g_epos[EE];   // original edge -> CSR slot
static __device__ __align__(16) int      g_row[NN + 1];
static __device__ __align__(16) int      g_woff[NN];
static __device__ __align__(16) int      g_cntI[NN];
static __device__ __align__(16) int      g_batch[NN];
static __device__ __align__(16) int      g_bsum[256];
static __device__ __align__(16) int      g_bpre[256];
static __device__           int          g_is32;

// ------------------------- helpers -------------------------
__device__ __forceinline__ float lrelu(float a) { return a > 0.f ? a : 0.2f * a; }

__device__ __forceinline__ unsigned long long bcast2(float v) {
    unsigned long long r;
    asm("mov.b64 %0, {%1, %1};" : "=l"(r) : "f"(v));
    return r;
}
__device__ __forceinline__ void ffma2(unsigned long long& d, unsigned long long a, unsigned long long b) {
    asm("fma.rn.f32x2 %0, %1, %2, %0;" : "+l"(d) : "l"(a), "l"(b));
}
__device__ __forceinline__ float2 unpack2(unsigned long long p) {
    float lo, hi;
    asm("mov.b64 {%0, %1}, %2;" : "=f"(lo), "=f"(hi) : "l"(p));
    return make_float2(lo, hi);
}

// ------------------------- setup kernels -------------------------
__global__ void k_zero() {
    int i = blockIdx.x * blockDim.x + threadIdx.x;
    if (i < NN) g_cntI[i] = 0;
    if (i < NG * HCDIM) g_pool[i] = 0.f;
}

// int64 little-endian layout: every odd 32-bit word is 0 (indices < 50000).
__global__ void k_detect(const unsigned* __restrict__ ei_raw) {
    __shared__ int nz;
    if (threadIdx.x == 0) nz = 0;
    __syncthreads();
    for (int k = threadIdx.x; k < 4096; k += 256)
        if (ei_raw[2 * k + 1] != 0u) nz = 1;
    __syncthreads();
    if (threadIdx.x == 0) g_is32 = nz;
}

__global__ void k_cvt(const void* __restrict__ ei_raw, const void* __restrict__ batch_raw) {
    int i = blockIdx.x * blockDim.x + threadIdx.x;
    int f = g_is32;
    if (i < EE) {
        int s, d;
        if (f) {
            s = ((const int*)ei_raw)[i];
            d = ((const int*)ei_raw)[EE + i];
        } else {
            s = (int)((const long long*)ei_raw)[i];
            d = (int)((const long long*)ei_raw)[EE + i];
        }
        g_src[i] = s;
        g_dst[i] = d;
        atomicAdd(&g_cntI[d], 1);
    }
    if (i < NN) {
        g_batch[i] = f ? ((const int*)batch_raw)[i]
                       : (int)((const long long*)batch_raw)[i];
    }
}

// ---- 3-phase parallel exclusive scan of g_cntI -> g_row / g_woff ----
__global__ void k_scan1() {
    __shared__ int sh[SCAN_B];
    int b = blockIdx.x, t = threadIdx.x;
    int i = b * SCAN_B + t;
    sh[t] = (i < NN) ? g_cntI[i] : 0;
    __syncthreads();
#pragma unroll
    for (int off = SCAN_B / 2; off; off >>= 1) {
        if (t < off) sh[t] += sh[t + off];
        __syncthreads();
    }
    if (t == 0) g_bsum[b] = sh[0];
}

__global__ void k_scan2() {   // 1 block, 256 threads; NBLK <= 256
    __shared__ int sh[256];
    int t = threadIdx.x;
    int v = (t < NBLK) ? g_bsum[t] : 0;
    sh[t] = v;
    __syncthreads();
#pragma unroll
    for (int off = 1; off < 256; off <<= 1) {
        int u = (t >= off) ? sh[t - off] : 0;
        __syncthreads();
        sh[t] += u;
        __syncthreads();
    }
    g_bpre[t] = sh[t] - v;           // exclusive
    if (t == 255) g_row[NN] = sh[255];
}

__global__ void k_scan3() {
    __shared__ int sh[SCAN_B];
    int b = blockIdx.x, t = threadIdx.x;
    int i = b * SCAN_B + t;
    int v = (i < NN) ? g_cntI[i] : 0;
    sh[t] = v;
    __syncthreads();
#pragma unroll
    for (int off = 1; off < SCAN_B; off <<= 1) {
        int u = (t >= off) ? sh[t - off] : 0;
        __syncthreads();
        sh[t] += u;
        __syncthreads();
    }
    if (i < NN) {
        int ex = g_bpre[b] + sh[t] - v;
        g_row[i] = ex;
        g_woff[i] = ex;
    }
}

__global__ void k_scatter() {
    int e = blockIdx.x * blockDim.x + threadIdx.x;
    if (e >= EE) return;
    int d = g_dst[e];
    int pos = atomicAdd(&g_woff[d], 1);
    g_epos[e] = pos;
    g_ssrc[pos] = g_src[e];
}

// ve[l][d*4+h] = sum_c We_l[d, h*16+c] * ae_l[h, c]
__global__ void k_ve(const float* __restrict__ We1, const float* __restrict__ ae1,
                     const float* __restrict__ We2, const float* __restrict__ ae2) {
    int t = threadIdx.x;           // 256 threads
    int l = t >> 7, r = t & 127, d = r >> 2, h = r & 3;
    const float* We = l ? We2 : We1;
    const float* ae = l ? ae2 : ae1;
    float s = 0.f;
#pragma unroll
    for (int c = 0; c < 16; c++) s += We[d * 64 + h * 16 + c] * ae[h * 16 + c];
    g_ve[l][d * 4 + h] = s;
}

// al_e for both layers, written in CSR order
__global__ void k_ale(const float* __restrict__ ea) {
    __shared__ float vs[2 * EDDIM * NH];   // 256 floats
    if (threadIdx.x < 256) vs[threadIdx.x] = ((const float*)g_ve)[threadIdx.x];
    __syncthreads();
    int e = blockIdx.x * blockDim.x + threadIdx.x;
    if (e >= EE) return;
    float ev[32];
    const float4* ep = (const float4*)(ea + (size_t)e * EDDIM);
#pragma unroll
    for (int q = 0; q < 8; q++) {
        float4 v = ep[q];
        ev[4 * q] = v.x; ev[4 * q + 1] = v.y; ev[4 * q + 2] = v.z; ev[4 * q + 3] = v.w;
    }
    float a1x = 0, a1y = 0, a1z = 0, a1w = 0;
    float a2x = 0, a2y = 0, a2z = 0, a2w = 0;
#pragma unroll
    for (int d = 0; d < 32; d++) {
        float x = ev[d];
        float4 w1 = *(const float4*)&vs[d * 4];
        float4 w2 = *(const float4*)&vs[128 + d * 4];
        a1x += x * w1.x; a1y += x * w1.y; a1z += x * w1.z; a1w += x * w1.w;
        a2x += x * w2.x; a2y += x * w2.y; a2z += x * w2.z; a2w += x * w2.w;
    }
    int pos = g_epos[e];
    *(float4*)&g_ale[0][(size_t)pos * 4] = make_float4(a1x, a1y, a1z, a1w);
    *(float4*)&g_ale[1][(size_t)pos * 4] = make_float4(a2x, a2y, a2z, a2w);
}

// ---- barrier-free GEMM, 8 rows x 4 cols per thread, 2 column-halves --------
// blockIdx.x = rowblk*2 + colhalf. Block covers 256 rows x 32 cols.
// W slice (KIN x 32) resident in smem; X streamed via LDG same-address bcast.
// Per k: 1 LDS.128 (ulonglong2 = col pairs) + 8 bcast + 16 FFMA2.
template <int KIN>
__global__ void __launch_bounds__(256, 3)
k_gemm(const float* __restrict__ Xext, const float* __restrict__ W,
       const float* __restrict__ as_, const float* __restrict__ ad_,
       int use_h1) {
    __shared__ float Ws[KIN * 32];       // 16KB (KIN=128) / 8KB (KIN=64)
    const float* X = use_h1 ? g_h1 : Xext;
    int t = threadIdx.x;
    int colhalf = blockIdx.x & 1;
    int rowblk  = blockIdx.x >> 1;
    // load W slice: Ws[k*32 + c] = W[k*64 + colhalf*32 + c]
    for (int i = t; i < KIN * 8; i += 256) {
        int k = i >> 3, q = i & 7;
        ((float4*)&Ws[k * 32])[q] = ((const float4*)&W[(size_t)k * HCDIM + colhalf * 32])[q];
    }
    __syncthreads();

    int rg = t >> 3;          // 0..31
    int cg = t & 7;           // 0..7  -> cols colhalf*32 + cg*4 .. +3
    int rbase = rowblk * GR + rg * 8;
    unsigned long long acc2[8][2];
#pragma unroll
    for (int i = 0; i < 8; i++) { acc2[i][0] = 0ull; acc2[i][1] = 0ull; }

#pragma unroll 2
    for (int q = 0; q < KIN / 4; q++) {
        float4 xq[8];
#pragma unroll
        for (int i = 0; i < 8; i++) {
            int grow = rbase + i;
            xq[i] = (grow < NN) ? __ldg((const float4*)&X[(size_t)grow * KIN + q * 4])
                                : make_float4(0.f, 0.f, 0.f, 0.f);
        }
#pragma unroll
        for (int v = 0; v < 4; v++) {
            int k = q * 4 + v;
            ulonglong2 w01 = *(const ulonglong2*)&Ws[k * 32 + cg * 4];
#pragma unroll
            for (int i = 0; i < 8; i++) {
                float xv = (v == 0) ? xq[i].x : (v == 1) ? xq[i].y : (v == 2) ? xq[i].z : xq[i].w;
                unsigned long long xb = bcast2(xv);
                ffma2(acc2[i][0], xb, w01.x);
                ffma2(acc2[i][1], xb, w01.y);
            }
        }
    }

    // alpha partials: this thread's 4 cols belong to head (colhalf*2 + (cg>>2)).
    int cbase = colhalf * 32 + cg * 4;
    float av[4], dv[4];
#pragma unroll
    for (int j = 0; j < 4; j++) {
        av[j] = __ldg(&as_[cbase + j]);
        dv[j] = __ldg(&ad_[cbase + j]);
    }
    int head = cbase >> 4;
#pragma unroll
    for (int i = 0; i < 8; i++) {
        float2 c01 = unpack2(acc2[i][0]);
        float2 c23 = unpack2(acc2[i][1]);
        float a[4] = {c01.x, c01.y, c23.x, c23.y};
        float sp = 0.f, dp = 0.f;
#pragma unroll
        for (int j = 0; j < 4; j++) { sp += a[j] * av[j]; dp += a[j] * dv[j]; }
        // head's 16 cols span the 4 threads cg&~3 .. cg|3 (same rg group)
        sp += __shfl_xor_sync(0xffffffffu, sp, 1);
        dp += __shfl_xor_sync(0xffffffffu, dp, 1);
        sp += __shfl_xor_sync(0xffffffffu, sp, 2);
        dp += __shfl_xor_sync(0xffffffffu, dp, 2);
        int grow = rbase + i;
        if (grow < NN) {
            *(float4*)&g_xw[(size_t)grow * HCDIM + cbase] = make_float4(a[0], a[1], a[2], a[3]);
            if ((cg & 3) == 0) {
                g_alsrc[(size_t)grow * 4 + head] = sp;
                g_aldst[(size_t)grow * 4 + head] = dp;
            }
        }
    }
}

// ------------------------- fused GAT aggregation: one warp per dst node -----
// (exact round-8 version — frozen)
template <int LAYER>
__global__ void k_main(const float* __restrict__ bias,
                       const float* __restrict__ gam, const float* __restrict__ bet) {
    __shared__ float4 s_alpha[8][32];
    int gw = (blockIdx.x * blockDim.x + threadIdx.x) >> 5;
    int lane = threadIdx.x & 31;
    int wl = (threadIdx.x >> 5);
    if (gw >= NN) return;
    int n = gw;
    int r0 = g_row[n], r1 = g_row[n + 1];
    int deg = r1 - r0;
    float4 adst = *(const float4*)&g_aldst[(size_t)n * 4];
    float4 asn  = *(const float4*)&g_alsrc[(size_t)n * 4];

    // ---- phase 1: sum(ale), max(alpha) over incoming edges ----
    float sx = 0.f, sy = 0.f, sz = 0.f, sw = 0.f;
    float mx = -1e30f, my = -1e30f, mz = -1e30f, mw = -1e30f;
    for (int k = r0 + lane; k < r1; k += 32) {
        int s = g_ssrc[k];
        float4 ae = *(const float4*)&g_ale[LAYER][(size_t)k * 4];
        float4 as = *(const float4*)&g_alsrc[(size_t)s * 4];
        sx += ae.x; sy += ae.y; sz += ae.z; sw += ae.w;
        float a0 = lrelu(as.x + adst.x + ae.x);
        float a1 = lrelu(as.y + adst.y + ae.y);
        float a2 = lrelu(as.z + adst.z + ae.z);
        float a3 = lrelu(as.w + adst.w + ae.w);
        if (k < r0 + 32) s_alpha[wl][lane] = make_float4(a0, a1, a2, a3);
        mx = fmaxf(mx, a0); my = fmaxf(my, a1); mz = fmaxf(mz, a2); mw = fmaxf(mw, a3);
    }
#pragma unroll
    for (int o = 16; o; o >>= 1) {
        sx += __shfl_xor_sync(0xffffffffu, sx, o);
        sy += __shfl_xor_sync(0xffffffffu, sy, o);
        sz += __shfl_xor_sync(0xffffffffu, sz, o);
        sw += __shfl_xor_sync(0xffffffffu, sw, o);
        mx = fmaxf(mx, __shfl_xor_sync(0xffffffffu, mx, o));
        my = fmaxf(my, __shfl_xor_sync(0xffffffffu, my, o));
        mz = fmaxf(mz, __shfl_xor_sync(0xffffffffu, mz, o));
        mw = fmaxf(mw, __shfl_xor_sync(0xffffffffu, mw, o));
    }
    float inv = 1.f / (float)(deg > 0 ? deg : 1);
    float ax0 = lrelu(asn.x + adst.x + sx * inv);
    float ax1 = lrelu(asn.y + adst.y + sy * inv);
    float ax2 = lrelu(asn.z + adst.z + sz * inv);
    float ax3 = lrelu(asn.w + adst.w + sw * inv);
    float AX = fmaxf(mx, ax0), AY = fmaxf(my, ax1), AZ = fmaxf(mz, ax2), AW = fmaxf(mw, ax3);
    float e0 = __expf(ax0 - AX), e1 = __expf(ax1 - AY), e2 = __expf(ax2 - AZ), e3 = __expf(ax3 - AW);

    // accumulators: channels c0=lane, c1=lane+32
    bool lo = lane < 16;
    float acc0 = g_xw[(size_t)n * 64 + lane]        * (lo ? e0 : e1);
    float acc1 = g_xw[(size_t)n * 64 + 32 + lane]   * (lo ? e2 : e3);
    float dnx = (lane == 0) ? e0 : 0.f, dny = (lane == 0) ? e1 : 0.f;
    float dnz = (lane == 0) ? e2 : 0.f, dnw = (lane == 0) ? e3 : 0.f;

    // ---- phase 2: exp + weighted gather-accumulate ----
    for (int base = r0; base < r1; base += 32) {
        int k = base + lane;
        int s = 0;
        float w0 = 0.f, w1 = 0.f, w2 = 0.f, w3 = 0.f;
        if (k < r1) {
            s = g_ssrc[k];
            float a0, a1, a2, a3;
            if (base == r0) {
                float4 al = s_alpha[wl][lane];
                a0 = al.x; a1 = al.y; a2 = al.z; a3 = al.w;
            } else {
                float4 ae = *(const float4*)&g_ale[LAYER][(size_t)k * 4];
                float4 as = *(const float4*)&g_alsrc[(size_t)s * 4];
                a0 = lrelu(as.x + adst.x + ae.x);
                a1 = lrelu(as.y + adst.y + ae.y);
                a2 = lrelu(as.z + adst.z + ae.z);
                a3 = lrelu(as.w + adst.w + ae.w);
            }
            w0 = __expf(a0 - AX); w1 = __expf(a1 - AY);
            w2 = __expf(a2 - AZ); w3 = __expf(a3 - AW);
            dnx += w0; dny += w1; dnz += w2; dnw += w3;
        }
        int m = r1 - base; if (m > 32) m = 32;
        for (int j = 0; j < m; j++) {
            int   sj = __shfl_sync(0xffffffffu, s, j);
            float qx = __shfl_sync(0xffffffffu, w0, j);
            float qy = __shfl_sync(0xffffffffu, w1, j);
            float qz = __shfl_sync(0xffffffffu, w2, j);
            float qw = __shfl_sync(0xffffffffu, w3, j);
            float wa = lo ? qx : qy;
            float wb = lo ? qz : qw;
            acc0 += wa * __ldg(&g_xw[(size_t)sj * 64 + lane]);
            acc1 += wb * __ldg(&g_xw[(size_t)sj * 64 + 32 + lane]);
        }
    }
#pragma unroll
    for (int o = 16; o; o >>= 1) {
        dnx += __shfl_xor_sync(0xffffffffu, dnx, o);
        dny += __shfl_xor_sync(0xffffffffu, dny, o);
        dnz += __shfl_xor_sync(0xffffffffu, dnz, o);
        dnw += __shfl_xor_sync(0xffffffffu, dnw, o);
    }
    float d0 = (lo ? dnx : dny) + 1e-16f;
    float d1 = (lo ? dnz : dnw) + 1e-16f;
    float v0 = fmaxf(acc0 / d0 + __ldg(&bias[lane]), 0.f);
    float v1 = fmaxf(acc1 / d1 + __ldg(&bias[lane + 32]), 0.f);

    if (LAYER == 0) {
        float su = v0 + v1, qu = v0 * v0 + v1 * v1;
#pragma unroll
        for (int o = 16; o; o >>= 1) {
            su += __shfl_xor_sync(0xffffffffu, su, o);
            qu += __shfl_xor_sync(0xffffffffu, qu, o);
        }
        float mean = su * (1.f / 64.f);
        float var = qu * (1.f / 64.f) - mean * mean;
        float rs = rsqrtf(var + 1e-5f);
        g_h1[(size_t)n * 64 + lane]      = (v0 - mean) * rs * __ldg(&gam[lane])      + __ldg(&bet[lane]);
        g_h1[(size_t)n * 64 + 32 + lane] = (v1 - mean) * rs * __ldg(&gam[lane + 32]) + __ldg(&bet[lane + 32]);
    } else {
        int g = g_batch[n];
        atomicMax((int*)&g_pool[g * 64 + lane],      __float_as_int(v0));
        atomicMax((int*)&g_pool[g * 64 + 32 + lane], __float_as_int(v1));
    }
}

// MLP head
__global__ void k_final(const float* __restrict__ fw1, const float* __restrict__ fb1,
                        const float* __restrict__ g2, const float* __restrict__ be2,
                        const float* __restrict__ fw2, const float* __restrict__ fb2,
                        float* __restrict__ out) {
    int g = blockIdx.x, j = threadIdx.x;   // 32 threads
    float z = fb1[j];
#pragma unroll 8
    for (int k = 0; k < 64; k++) z += g_pool[g * 64 + k] * fw1[k * 32 + j];
    float s = z;
#pragma unroll
    for (int o = 16; o; o >>= 1) s += __shfl_xor_sync(0xffffffffu, s, o);
    float mean = s * (1.f / 32.f);
    float dd = z - mean;
    float q = dd * dd;
#pragma unroll
    for (int o = 16; o; o >>= 1) q += __shfl_xor_sync(0xffffffffu, q, o);
    float var = q * (1.f / 32.f);
    float y = fmaxf(dd * rsqrtf(var + 1e-5f) * g2[j] + be2[j], 0.f);
    float p0 = y * fw2[j * 2 + 0];
    float p1 = y * fw2[j * 2 + 1];
#pragma unroll
    for (int o = 16; o; o >>= 1) {
        p0 += __shfl_xor_sync(0xffffffffu, p0, o);
        p1 += __shfl_xor_sync(0xffffffffu, p1, o);
    }
    if (j == 0) {
        float z0 = p0 + fb2[0], z1 = p1 + fb2[1];
        float m = fmaxf(z0, z1);
        float lse = m + __logf(__expf(z0 - m) + __expf(z1 - m));
        out[g * 2 + 0] = z0 - lse;
        out[g * 2 + 1] = z1 - lse;
    }
}

// ------------------------- launch -------------------------
extern "C" void kernel_launch(void* const* d_in, const int* in_sizes, int n_in,
                              void* d_out, int out_size) {
    (void)in_sizes; (void)n_in; (void)out_size;
    const float* x   = (const float*)d_in[0];
    const float* ea  = (const float*)d_in[1];
    const float* W1  = (const float*)d_in[2];
    const float* as1 = (const float*)d_in[3];
    const float* ad1 = (const float*)d_in[4];
    const float* We1 = (const float*)d_in[5];
    const float* ae1 = (const float*)d_in[6];
    const float* b1  = (const float*)d_in[7];
    const float* W2  = (const float*)d_in[8];
    const float* as2 = (const float*)d_in[9];
    const float* ad2 = (const float*)d_in[10];
    const float* We2 = (const float*)d_in[11];
    const float* ae2 = (const float*)d_in[12];
    const float* b2  = (const float*)d_in[13];
    const float* g1  = (const float*)d_in[14];
    const float* be1 = (const float*)d_in[15];
    const float* fw1 = (const float*)d_in[16];
    const float* fb1 = (const float*)d_in[17];
    const float* g2  = (const float*)d_in[18];
    const float* be2 = (const float*)d_in[19];
    const float* fw2 = (const float*)d_in[20];
    const float* fb2 = (const float*)d_in[21];
    const void* ei_raw    = d_in[22];
    const void* batch_raw = d_in[23];
    float* out = (float*)d_out;

    const int TB = 256;
    int nb_nh = (NN * NH + TB - 1) / TB;
    int nb_e  = (EE + TB - 1) / TB;
    int nb_w  = (NN * 32 + TB - 1) / TB;       // warp per node
    int nb_g  = ((NN + GR - 1) / GR) * 2;      // gemm blocks (196 rowblks x 2 colhalves)

    k_zero<<<nb_nh, TB>>>();
    k_detect<<<1, 256>>>((const unsigned*)ei_raw);
    k_cvt<<<nb_e, TB>>>(ei_raw, batch_raw);
    // 4th launch stays k_gemm<128> (profiled control)
    k_gemm<INDIM><<<nb_g, TB>>>(x, W1, as1, ad1, 0);
    k_scan1<<<NBLK, SCAN_B>>>();
    k_scan2<<<1, 256>>>();
    k_scan3<<<NBLK, SCAN_B>>>();
    k_scatter<<<nb_e, TB>>>();
    k_ve<<<1, 256>>>(We1, ae1, We2, ae2);
    k_ale<<<nb_e, TB>>>(ea);

    // ---- layer 1 aggregation ----
    k_main<0><<<nb_w, TB>>>(b1, g1, be1);

    // ---- layer 2 ----
    k_gemm<HCDIM><<<nb_g, TB>>>(nullptr, W2, as2, ad2, 1);
    k_main<1><<<nb_w, TB>>>(b2, nullptr, nullptr);

    // ---- head ----
    k_final<<<NG, 32>>>(fw1, fb1, g2, be2, fw2, fb2, out);
}